// round 9
// baseline (speedup 1.0000x reference)
#include <cuda_runtime.h>

#define NN   50000
#define FD   96
#define EMAX 800000
#define SCAN_BLK 512
#define SCAN_NB  ((NN + SCAN_BLK - 1) / SCAN_BLK)   // 98

// ---- device scratch: accessed ONLY from device code ----
__device__ __align__(16) float sg_msg1[NN * 96];
__device__ __align__(16) float sg_root1[NN * 96];
__device__ __align__(16) float sg_hid[NN * 96];
__device__ __align__(16) float sg_msg2[NN * 48];
__device__ __align__(16) float sg_root2[NN * 48];
__device__ __align__(16) float sg_wtd1[FD * 384];  // k-major, duplicated: [k][2c]=[k][2c+1]=w[c], OUTT=192
__device__ __align__(16) float sg_wtd2[FD * 192];  // same for OUTT=96
__device__ int sg_deg[NN];
__device__ int sg_rowptr[NN + 1];
__device__ int sg_cursor[NN];
__device__ int sg_adj[EMAX];
__device__ int sg_part[SCAN_NB];
__device__ int sg_off[SCAN_NB];
__device__ int sg_is64;

__device__ __forceinline__ float* sg_sel(int w) {
    switch (w) {
        case 0: return sg_msg1;
        case 1: return sg_root1;
        case 2: return sg_hid;
        case 3: return sg_msg2;
        case 4: return sg_root2;
        case 5: return sg_wtd1;
        default: return sg_wtd2;
    }
}

// packed fp32x2 FMA (FFMA2): d = a*b + d elementwise on two floats
__device__ __forceinline__ void ffma2(unsigned long long& d,
                                      unsigned long long a,
                                      unsigned long long b) {
    asm("fma.rn.f32x2 %0, %1, %2, %3;" : "=l"(d) : "l"(a), "l"(b), "l"(d));
}

// ---- init: zero deg + dtype sniff ----
__global__ void sgv9_init(const int* __restrict__ ei32, int n32) {
    int i = blockIdx.x * blockDim.x + threadIdx.x;
    if (i < NN) sg_deg[i] = 0;
    if (i == 0) {
        int nz = 0;
        int lim = (n32 < 1024) ? n32 : 1024;
        for (int j = 1; j < lim; j += 2) nz |= (ei32[j] != 0);
        sg_is64 = nz ? 0 : 1;
    }
}

// ---- weight transpose + duplicate into k-major scratch ----
__global__ void sgv9_wtrans(const float* __restrict__ w1_l, const float* __restrict__ w1_r,
                            const float* __restrict__ w2_l, const float* __restrict__ w2_r) {
    int stride = gridDim.x * blockDim.x;
    for (int i = blockIdx.x * blockDim.x + threadIdx.x; i < FD * 192 + FD * 96; i += stride) {
        if (i < FD * 192) {
            int k = i / 192, o = i % 192;
            float v = (o < 96) ? w1_l[o * FD + k] : w1_r[(o - 96) * FD + k];
            sg_wtd1[k * 384 + 2 * o] = v;
            sg_wtd1[k * 384 + 2 * o + 1] = v;
        } else {
            int j = i - FD * 192;
            int k = j / 96, o = j % 96;
            float v = (o < 48) ? w2_l[o * FD + k] : w2_r[(o - 48) * FD + k];
            sg_wtd2[k * 192 + 2 * o] = v;
            sg_wtd2[k * 192 + 2 * o + 1] = v;
        }
    }
}

__device__ __forceinline__ int sgv9_edge(const void* ei, int idx, int is64) {
    int v = is64 ? (int)((const long long*)ei)[idx] : ((const int*)ei)[idx];
    return min(max(v, 0), NN - 1);
}

__global__ void sgv9_count(const void* __restrict__ ei, int E) {
    int stride = gridDim.x * blockDim.x;
    int is64 = sg_is64;
    for (int e = blockIdx.x * blockDim.x + threadIdx.x; e < E; e += stride)
        atomicAdd(&sg_deg[sgv9_edge(ei, e + E, is64)], 1);
}

// ---- 3-phase scan ----
__global__ void __launch_bounds__(SCAN_BLK) sgv9_scan_a() {
    __shared__ int sm[SCAN_BLK];
    int t = threadIdx.x;
    int i = blockIdx.x * SCAN_BLK + t;
    sm[t] = (i < NN) ? sg_deg[i] : 0;
    __syncthreads();
    for (int off = SCAN_BLK / 2; off > 0; off >>= 1) {
        if (t < off) sm[t] += sm[t + off];
        __syncthreads();
    }
    if (t == 0) sg_part[blockIdx.x] = sm[0];
}

__global__ void __launch_bounds__(128) sgv9_scan_b() {
    __shared__ int sm[128];
    int t = threadIdx.x;
    int v = (t < SCAN_NB) ? sg_part[t] : 0;
    sm[t] = v;
    __syncthreads();
    for (int off = 1; off < 128; off <<= 1) {
        int add = (t >= off) ? sm[t - off] : 0;
        __syncthreads();
        sm[t] += add;
        __syncthreads();
    }
    if (t < SCAN_NB) sg_off[t] = sm[t] - v;
    if (t == 127) sg_rowptr[NN] = sm[127];
}

__global__ void __launch_bounds__(SCAN_BLK) sgv9_scan_c() {
    __shared__ int sm[SCAN_BLK];
    int t = threadIdx.x;
    int i = blockIdx.x * SCAN_BLK + t;
    int v = (i < NN) ? sg_deg[i] : 0;
    sm[t] = v;
    __syncthreads();
    for (int off = 1; off < SCAN_BLK; off <<= 1) {
        int add = (t >= off) ? sm[t - off] : 0;
        __syncthreads();
        sm[t] += add;
        __syncthreads();
    }
    if (i < NN) {
        int excl = sg_off[blockIdx.x] + sm[t] - v;
        sg_rowptr[i] = excl;
        sg_cursor[i] = excl;
    }
}

__global__ void sgv9_bucket(const void* __restrict__ ei, int E) {
    int stride = gridDim.x * blockDim.x;
    int is64 = sg_is64;
    for (int e = blockIdx.x * blockDim.x + threadIdx.x; e < E; e += stride) {
        int d = sgv9_edge(ei, e + E, is64);
        int s = sgv9_edge(ei, e, is64);
        int p = atomicAdd(&sg_cursor[d], 1);
        sg_adj[p] = s;
    }
}

// ---- dual GEMM (FFMA2): [Oa|Ob](row,:) = X(row,:) @ W, W duplicated k-major ----
// Thread: 8 rows x 4 cols as 4 row-pairs x 4 cols of packed f32x2.
// xs k-major in smem -> LDS.64 gives (x_r, x_{r+1}); WTD LDG.128 gives 2x (w_c, w_c).
template <int OUTT, int S, int XSEL, int WSEL, int OA, int OB>
__global__ void __launch_bounds__(192) sgv9_gemm(const float* __restrict__ Xin) {
    const int TQ = OUTT / 4;        // 48 or 24
    const int TY = 192 / TQ;        // 4 or 8
    const int ROWS = TY * 8;        // 32 or 64
    const int XR = ROWS + 2;        // even padding (keeps LDS.64 alignment)

    __shared__ __align__(16) float xs[FD * XR];   // 13.1 KB / 25.3 KB static

    const float* X = (XSEL < 0) ? Xin : sg_sel(XSEL);
    const float* WTD = sg_sel(WSEL);
    float* Oa = sg_sel(OA);
    float* Ob = sg_sel(OB);

    int tid = threadIdx.x;
    int R0 = blockIdx.x * ROWS;

    // load X tile transposed: xs[k][r]  (coalesced global float4 reads)
    for (int i = tid; i < ROWS * (FD / 4); i += 192) {
        int r = i / (FD / 4), kc = i % (FD / 4);
        int row = R0 + r;
        float4 v = (row < NN) ? ((const float4*)(X + (size_t)row * FD))[kc]
                              : make_float4(0.f, 0.f, 0.f, 0.f);
        xs[(kc * 4 + 0) * XR + r] = v.x;
        xs[(kc * 4 + 1) * XR + r] = v.y;
        xs[(kc * 4 + 2) * XR + r] = v.z;
        xs[(kc * 4 + 3) * XR + r] = v.w;
    }
    __syncthreads();

    int tx = tid % TQ, ty = tid / TQ;
    int c0 = tx * 4, r0 = ty * 8;

    unsigned long long acc[4][4];
#pragma unroll
    for (int p = 0; p < 4; p++)
#pragma unroll
        for (int c = 0; c < 4; c++) acc[p][c] = 0ull;

    const int WROW = OUTT * 2;
#pragma unroll 4
    for (int k = 0; k < FD; k++) {
        ulonglong2 wv0 = *(const ulonglong2*)&WTD[k * WROW + c0 * 2];      // (w_c0,w_c0),(w_c1,w_c1)
        ulonglong2 wv1 = *(const ulonglong2*)&WTD[k * WROW + c0 * 2 + 4];  // (w_c2,..),(w_c3,..)
        unsigned long long xp0 = *(const unsigned long long*)&xs[k * XR + r0];
        unsigned long long xp1 = *(const unsigned long long*)&xs[k * XR + r0 + 2];
        unsigned long long xp2 = *(const unsigned long long*)&xs[k * XR + r0 + 4];
        unsigned long long xp3 = *(const unsigned long long*)&xs[k * XR + r0 + 6];
        ffma2(acc[0][0], xp0, wv0.x); ffma2(acc[0][1], xp0, wv0.y);
        ffma2(acc[0][2], xp0, wv1.x); ffma2(acc[0][3], xp0, wv1.y);
        ffma2(acc[1][0], xp1, wv0.x); ffma2(acc[1][1], xp1, wv0.y);
        ffma2(acc[1][2], xp1, wv1.x); ffma2(acc[1][3], xp1, wv1.y);
        ffma2(acc[2][0], xp2, wv0.x); ffma2(acc[2][1], xp2, wv0.y);
        ffma2(acc[2][2], xp2, wv1.x); ffma2(acc[2][3], xp2, wv1.y);
        ffma2(acc[3][0], xp3, wv0.x); ffma2(acc[3][1], xp3, wv0.y);
        ffma2(acc[3][2], xp3, wv1.x); ffma2(acc[3][3], xp3, wv1.y);
    }

    const int HALF = OUTT / 2;
    float* Obase = (c0 < HALF) ? (Oa + c0) : (Ob + (c0 - HALF));
#pragma unroll
    for (int p = 0; p < 4; p++) {
        float2 f0 = *(float2*)&acc[p][0];
        float2 f1 = *(float2*)&acc[p][1];
        float2 f2 = *(float2*)&acc[p][2];
        float2 f3 = *(float2*)&acc[p][3];
        int rowA = R0 + r0 + 2 * p;
        if (rowA < NN)
            *(float4*)&Obase[(size_t)rowA * S] = make_float4(f0.x, f1.x, f2.x, f3.x);
        if (rowA + 1 < NN)
            *(float4*)&Obase[(size_t)(rowA + 1) * S] = make_float4(f0.y, f1.y, f2.y, f3.y);
    }
}

// ---- fused gather + epilogue ----
template <int OUT, int RELU, int VSEL, int RSEL, int OSEL>
__global__ void __launch_bounds__(256) sgv9_gather(const float* __restrict__ bias,
                                                   float* __restrict__ Oext) {
    const int SUBW = (OUT == 96) ? 32 : 16;
    const int VQ = OUT / 4;
    int t = blockIdx.x * 256 + threadIdx.x;
    int node = t / SUBW;
    int sl = t % SUBW;
    if (node >= NN || sl >= VQ) return;

    const float4* V4 = (const float4*)sg_sel(VSEL);
    const float* root = sg_sel(RSEL);
    float* O = (OSEL < 0) ? Oext : sg_sel(OSEL);

    int beg = sg_rowptr[node], end = sg_rowptr[node + 1];

    float4 a = make_float4(0.f, 0.f, 0.f, 0.f);
    float4 b = make_float4(0.f, 0.f, 0.f, 0.f);
    int j = beg;
    for (; j + 1 < end; j += 2) {
        float4 r0 = V4[(size_t)sg_adj[j] * VQ + sl];
        float4 r1 = V4[(size_t)sg_adj[j + 1] * VQ + sl];
        a.x += r0.x; a.y += r0.y; a.z += r0.z; a.w += r0.w;
        b.x += r1.x; b.y += r1.y; b.z += r1.z; b.w += r1.w;
    }
    if (j < end) {
        float4 r0 = V4[(size_t)sg_adj[j] * VQ + sl];
        a.x += r0.x; a.y += r0.y; a.z += r0.z; a.w += r0.w;
    }
    float inv = 1.f / fmaxf((float)(end - beg), 1.f);
    float4 rt = *(const float4*)&root[(size_t)node * OUT + sl * 4];
    float4 bb = *(const float4*)&bias[sl * 4];
    float4 v;
    v.x = (a.x + b.x) * inv + rt.x + bb.x;
    v.y = (a.y + b.y) * inv + rt.y + bb.y;
    v.z = (a.z + b.z) * inv + rt.z + bb.z;
    v.w = (a.w + b.w) * inv + rt.w + bb.w;
    if (RELU) {
        v.x = fmaxf(v.x, 0.f); v.y = fmaxf(v.y, 0.f);
        v.z = fmaxf(v.z, 0.f); v.w = fmaxf(v.w, 0.f);
    }
    *(float4*)&O[(size_t)node * OUT + sl * 4] = v;
}

extern "C" void kernel_launch(void* const* d_in, const int* in_sizes, int n_in,
                              void* d_out, int out_size) {
    const float* x    = (const float*)d_in[0];
    const void*  ei   = d_in[1];
    const float* w1_l = (const float*)d_in[2];
    const float* b1   = (const float*)d_in[3];
    const float* w1_r = (const float*)d_in[4];
    const float* w2_l = (const float*)d_in[5];
    const float* b2   = (const float*)d_in[6];
    const float* w2_r = (const float*)d_in[7];
    float*       out  = (float*)d_out;

    int E = in_sizes[1] / 2;
    if (E > EMAX) E = EMAX;

    const int g1_blocks = (NN + 31) / 32;            // OUTT=192, ROWS=32
    const int g2_blocks = (NN + 63) / 64;            // OUTT=96,  ROWS=64
    const int ga96_blocks = (NN * 32 + 255) / 256;
    const int ga48_blocks = (NN * 16 + 255) / 256;

    sgv9_init<<<SCAN_NB, SCAN_BLK>>>((const int*)ei, in_sizes[1]);
    sgv9_wtrans<<<64, 256>>>(w1_l, w1_r, w2_l, w2_r);
    sgv9_count<<<1024, 256>>>(ei, E);
    // heavy GEMM as launch #4 (profiler window)
    sgv9_gemm<192, 96, -1, 5, 0, 1><<<g1_blocks, 192>>>(x);
    sgv9_scan_a<<<SCAN_NB, SCAN_BLK>>>();
    sgv9_scan_b<<<1, 128>>>();
    sgv9_scan_c<<<SCAN_NB, SCAN_BLK>>>();
    sgv9_bucket<<<1024, 256>>>(ei, E);

    // Layer 1: hid = relu(mean(msg1) + b1 + root1)
    sgv9_gather<96, 1, 0, 1, 2><<<ga96_blocks, 256>>>(b1, nullptr);

    // Layer 2: [msg2|root2] = hid @ wtd2 ; out = mean(msg2) + b2 + root2
    sgv9_gemm<96, 48, 2, 6, 3, 4><<<g2_blocks, 192>>>(nullptr);
    sgv9_gather<48, 0, 3, 4, -1><<<ga48_blocks, 256>>>(b2, out);
}

// round 11
// speedup vs baseline: 1.1598x; 1.1598x over previous
#include <cuda_runtime.h>
#include <cuda_fp16.h>
#include <cstdint>

#define NN   50000
#define FD   96
#define EMAX 800000
#define SCAN_BLK 512
#define SCAN_NB  ((NN + SCAN_BLK - 1) / SCAN_BLK)   // 98

// ---- device scratch: accessed ONLY from device code ----
__device__ __align__(16) __half sgh_msg1[NN * 96];  // x@w1_l^T (fp16)
__device__ __align__(16) __half sgh_msg2[NN * 48];  // hid@w2_l^T (fp16)
__device__ __align__(16) float sg_root1[NN * 96];   // x@w1_r^T
__device__ __align__(16) float sg_hid[NN * 96];     // layer-1 out
__device__ __align__(16) float sg_root2[NN * 48];   // hid@w2_r^T
__device__ __align__(16) float sg_wt1[FD * 192];    // k-major concat(w1_l,w1_r)
__device__ __align__(16) float sg_wt2[FD * 96];     // k-major concat(w2_l,w2_r)
__device__ int sg_deg[NN];
__device__ int sg_rowptr[NN + 1];
__device__ int sg_cursor[NN];
__device__ int sg_adj[EMAX];
__device__ int sg_src[EMAX];
__device__ int sg_dst[EMAX];
__device__ int sg_part[SCAN_NB];
__device__ int sg_off[SCAN_NB];
__device__ int sg_is64;

__device__ __forceinline__ float* sg_sel(int w) {
    switch (w) {
        case 0: return sg_root1;
        case 1: return sg_hid;
        case 2: return sg_root2;
        case 3: return sg_wt1;
        default: return sg_wt2;
    }
}
__device__ __forceinline__ __half* sgh_sel(int w) {
    return (w == 0) ? sgh_msg1 : sgh_msg2;
}

// ---- init: zero deg + dtype sniff (int64 edges have all-zero high words) ----
__global__ void sgv11_init(const int* __restrict__ ei32, int n32) {
    int i = blockIdx.x * blockDim.x + threadIdx.x;
    if (i < NN) sg_deg[i] = 0;
    if (i == 0) {
        int nz = 0;
        int lim = (n32 < 1024) ? n32 : 1024;
        for (int j = 1; j < lim; j += 2) nz |= (ei32[j] != 0);
        sg_is64 = nz ? 0 : 1;
    }
}

// ---- weight transpose into k-major scratch ----
__global__ void sgv11_wtrans(const float* __restrict__ w1_l, const float* __restrict__ w1_r,
                             const float* __restrict__ w2_l, const float* __restrict__ w2_r) {
    int stride = gridDim.x * blockDim.x;
    for (int i = blockIdx.x * blockDim.x + threadIdx.x; i < FD * 192 + FD * 96; i += stride) {
        if (i < FD * 192) {
            int k = i / 192, o = i % 192;
            sg_wt1[i] = (o < 96) ? w1_l[o * FD + k] : w1_r[(o - 96) * FD + k];
        } else {
            int j = i - FD * 192;
            int k = j / 96, o = j % 96;
            sg_wt2[j] = (o < 48) ? w2_l[o * FD + k] : w2_r[(o - 48) * FD + k];
        }
    }
}

__device__ __forceinline__ int sgv11_edge(const void* ei, int idx, int is64) {
    int v = is64 ? (int)((const long long*)ei)[idx] : ((const int*)ei)[idx];
    return min(max(v, 0), NN - 1);
}

// ---- stage edges to clamped int32 + count degrees (fused) ----
__global__ void sgv11_stage(const void* __restrict__ ei, int E) {
    int stride = gridDim.x * blockDim.x;
    int is64 = sg_is64;
    for (int e = blockIdx.x * blockDim.x + threadIdx.x; e < E; e += stride) {
        int s = sgv11_edge(ei, e, is64);
        int d = sgv11_edge(ei, e + E, is64);
        sg_src[e] = s;
        sg_dst[e] = d;
        atomicAdd(&sg_deg[d], 1);
    }
}

// ---- 3-phase scan ----
__global__ void __launch_bounds__(SCAN_BLK) sgv11_scan_a() {
    __shared__ int sm[SCAN_BLK];
    int t = threadIdx.x;
    int i = blockIdx.x * SCAN_BLK + t;
    sm[t] = (i < NN) ? sg_deg[i] : 0;
    __syncthreads();
    for (int off = SCAN_BLK / 2; off > 0; off >>= 1) {
        if (t < off) sm[t] += sm[t + off];
        __syncthreads();
    }
    if (t == 0) sg_part[blockIdx.x] = sm[0];
}

__global__ void __launch_bounds__(128) sgv11_scan_b() {
    __shared__ int sm[128];
    int t = threadIdx.x;
    int v = (t < SCAN_NB) ? sg_part[t] : 0;
    sm[t] = v;
    __syncthreads();
    for (int off = 1; off < 128; off <<= 1) {
        int add = (t >= off) ? sm[t - off] : 0;
        __syncthreads();
        sm[t] += add;
        __syncthreads();
    }
    if (t < SCAN_NB) sg_off[t] = sm[t] - v;
    if (t == 127) sg_rowptr[NN] = sm[127];
}

__global__ void __launch_bounds__(SCAN_BLK) sgv11_scan_c() {
    __shared__ int sm[SCAN_BLK];
    int t = threadIdx.x;
    int i = blockIdx.x * SCAN_BLK + t;
    int v = (i < NN) ? sg_deg[i] : 0;
    sm[t] = v;
    __syncthreads();
    for (int off = 1; off < SCAN_BLK; off <<= 1) {
        int add = (t >= off) ? sm[t - off] : 0;
        __syncthreads();
        sm[t] += add;
        __syncthreads();
    }
    if (i < NN) {
        int excl = sg_off[blockIdx.x] + sm[t] - v;
        sg_rowptr[i] = excl;
        sg_cursor[i] = excl;
    }
}

__global__ void sgv11_bucket(int E) {
    int stride = gridDim.x * blockDim.x;
    for (int e = blockIdx.x * blockDim.x + threadIdx.x; e < E; e += stride) {
        int p = atomicAdd(&sg_cursor[sg_dst[e]], 1);
        sg_adj[p] = sg_src[e];
    }
}

// ---- dual GEMM (R8 mainloop): [Msg(fp16) | Root(fp32)](row,:) = X(row,:) @ WT ----
// WT k-major [FD][OUTT]. Thread: 8 rows x 4 cols. X tile in static smem;
// W streamed via LDG.128 (L1-resident). Cols [0,HALF) -> fp16 msg, rest fp32 root.
template <int OUTT, int XSEL, int WSEL, int HSEL, int RSEL>
__global__ void __launch_bounds__(192, 4) sgv11_gemm(const float* __restrict__ Xin) {
    const int TQ = OUTT / 4;        // 48 or 24
    const int TY = 192 / TQ;        // 4 or 8
    const int ROWS = TY * 8;        // 32 or 64
    const int XP = FD + 4;          // 100
    const int HALF = OUTT / 2;

    __shared__ __align__(16) float xs[ROWS * XP];

    const float* X = (XSEL < 0) ? Xin : sg_sel(XSEL);
    const float* WT = sg_sel(WSEL);
    __half* H = sgh_sel(HSEL);
    float* R = sg_sel(RSEL);

    int tid = threadIdx.x;
    int R0 = blockIdx.x * ROWS;

    for (int i = tid; i < ROWS * (FD / 4); i += 192) {
        int r = i / (FD / 4), kc = i % (FD / 4);
        int row = R0 + r;
        float4 v = (row < NN) ? ((const float4*)(X + (size_t)row * FD))[kc]
                              : make_float4(0.f, 0.f, 0.f, 0.f);
        *(float4*)&xs[r * XP + kc * 4] = v;
    }
    __syncthreads();

    int tx = tid % TQ, ty = tid / TQ;
    int c0 = tx * 4, r0 = ty * 8;

    float acc[8][4];
#pragma unroll
    for (int i = 0; i < 8; i++)
#pragma unroll
        for (int j = 0; j < 4; j++) acc[i][j] = 0.f;

#pragma unroll 4
    for (int k = 0; k < FD; k++) {
        float4 w = *(const float4*)&WT[k * OUTT + c0];
#pragma unroll
        for (int i = 0; i < 8; i++) {
            float xv = xs[(r0 + i) * XP + k];
            acc[i][0] = fmaf(w.x, xv, acc[i][0]);
            acc[i][1] = fmaf(w.y, xv, acc[i][1]);
            acc[i][2] = fmaf(w.z, xv, acc[i][2]);
            acc[i][3] = fmaf(w.w, xv, acc[i][3]);
        }
    }

    if (c0 < HALF) {
#pragma unroll
        for (int i = 0; i < 8; i++) {
            int row = R0 + r0 + i;
            if (row >= NN) break;
            __half2 h0 = __floats2half2_rn(acc[i][0], acc[i][1]);
            __half2 h1 = __floats2half2_rn(acc[i][2], acc[i][3]);
            __half2* p = (__half2*)&H[(size_t)row * HALF + c0];
            p[0] = h0;
            p[1] = h1;
        }
    } else {
#pragma unroll
        for (int i = 0; i < 8; i++) {
            int row = R0 + r0 + i;
            if (row >= NN) break;
            *(float4*)&R[(size_t)row * HALF + (c0 - HALF)] =
                make_float4(acc[i][0], acc[i][1], acc[i][2], acc[i][3]);
        }
    }
}

// ---- fused gather (fp16 msgs) + epilogue (fp32) ----
// O[node] = relu?( mean_j msg[adj[j]] + bias + root[node] )
template <int OUT, int RELU, int HSEL, int RSEL, int OSEL>
__global__ void __launch_bounds__(256) sgv11_gather(const float* __restrict__ bias,
                                                    float* __restrict__ Oext) {
    const int SUBW = (OUT == 96) ? 32 : 16;
    const int VQ = OUT / 4;        // active lanes: 24 or 12
    int t = blockIdx.x * 256 + threadIdx.x;
    int node = t / SUBW;
    int sl = t % SUBW;
    if (node >= NN || sl >= VQ) return;

    const __half* Vh = sgh_sel(HSEL);
    const float* root = sg_sel(RSEL);
    float* O = (OSEL < 0) ? Oext : sg_sel(OSEL);

    int beg = sg_rowptr[node], end = sg_rowptr[node + 1];

    float4 a = make_float4(0.f, 0.f, 0.f, 0.f);
    float4 b = make_float4(0.f, 0.f, 0.f, 0.f);
    int j = beg;
    for (; j + 1 < end; j += 2) {
        uint2 u0 = *(const uint2*)&Vh[(size_t)sg_adj[j] * OUT + sl * 4];
        uint2 u1 = *(const uint2*)&Vh[(size_t)sg_adj[j + 1] * OUT + sl * 4];
        float2 f00 = __half22float2(*(__half2*)&u0.x);
        float2 f01 = __half22float2(*(__half2*)&u0.y);
        float2 f10 = __half22float2(*(__half2*)&u1.x);
        float2 f11 = __half22float2(*(__half2*)&u1.y);
        a.x += f00.x; a.y += f00.y; a.z += f01.x; a.w += f01.y;
        b.x += f10.x; b.y += f10.y; b.z += f11.x; b.w += f11.y;
    }
    if (j < end) {
        uint2 u0 = *(const uint2*)&Vh[(size_t)sg_adj[j] * OUT + sl * 4];
        float2 f00 = __half22float2(*(__half2*)&u0.x);
        float2 f01 = __half22float2(*(__half2*)&u0.y);
        a.x += f00.x; a.y += f00.y; a.z += f01.x; a.w += f01.y;
    }
    float inv = 1.f / fmaxf((float)(end - beg), 1.f);
    float4 rt = *(const float4*)&root[(size_t)node * OUT + sl * 4];
    float4 bb = *(const float4*)&bias[sl * 4];
    float4 v;
    v.x = (a.x + b.x) * inv + rt.x + bb.x;
    v.y = (a.y + b.y) * inv + rt.y + bb.y;
    v.z = (a.z + b.z) * inv + rt.z + bb.z;
    v.w = (a.w + b.w) * inv + rt.w + bb.w;
    if (RELU) {
        v.x = fmaxf(v.x, 0.f); v.y = fmaxf(v.y, 0.f);
        v.z = fmaxf(v.z, 0.f); v.w = fmaxf(v.w, 0.f);
    }
    *(float4*)&O[(size_t)node * OUT + sl * 4] = v;
}

extern "C" void kernel_launch(void* const* d_in, const int* in_sizes, int n_in,
                              void* d_out, int out_size) {
    const float* x    = (const float*)d_in[0];
    const void*  ei   = d_in[1];
    const float* w1_l = (const float*)d_in[2];
    const float* b1   = (const float*)d_in[3];
    const float* w1_r = (const float*)d_in[4];
    const float* w2_l = (const float*)d_in[5];
    const float* b2   = (const float*)d_in[6];
    const float* w2_r = (const float*)d_in[7];
    float*       out  = (float*)d_out;

    int E = in_sizes[1] / 2;
    if (E > EMAX) E = EMAX;

    const int g1_blocks = (NN + 31) / 32;            // OUTT=192, ROWS=32
    const int g2_blocks = (NN + 63) / 64;            // OUTT=96,  ROWS=64
    const int ga96_blocks = (NN * 32 + 255) / 256;
    const int ga48_blocks = (NN * 16 + 255) / 256;

    sgv11_init<<<SCAN_NB, SCAN_BLK>>>((const int*)ei, in_sizes[1]);
    sgv11_wtrans<<<64, 256>>>(w1_l, w1_r, w2_l, w2_r);
    sgv11_stage<<<1024, 256>>>(ei, E);
    // heavy GEMM as launch #4 (profiler window)
    sgv11_gemm<192, -1, 3, 0, 0><<<g1_blocks, 192>>>(x);
    sgv11_scan_a<<<SCAN_NB, SCAN_BLK>>>();
    sgv11_scan_b<<<1, 128>>>();
    sgv11_scan_c<<<SCAN_NB, SCAN_BLK>>>();
    sgv11_bucket<<<1024, 256>>>(E);

    // Layer 1: hid = relu(mean(msg1) + b1 + root1)
    sgv11_gather<96, 1, 0, 0, 1><<<ga96_blocks, 256>>>(b1, nullptr);

    // Layer 2: [msg2(fp16) | root2] = hid @ wt2 ; out = mean(msg2) + b2 + root2
    sgv11_gemm<96, 1, 4, 1, 2><<<g2_blocks, 192>>>(nullptr);
    sgv11_gather<48, 0, 1, 2, -1><<<ga48_blocks, 256>>>(b2, out);
}